// round 2
// baseline (speedup 1.0000x reference)
#include <cuda_runtime.h>

#define BATCH 131072
#define NNEI 20
#define NFEAT 172
#define NTIME 100

// ---- scratch (device globals; no allocations) ----
__device__ float g_qs[(size_t)BATCH * 100];      // scaled q
__device__ float g_A[(size_t)BATCH * 548];       // per-batch folded score matrix (2 heads x 273, col272 = bias)
__device__ float g_m[(size_t)BATCH * 544];       // weighted kv sums
__device__ unsigned char g_invalid[BATCH];
__device__ float g_W1[100 * 128];                // Wq^T, padded cols
__device__ float g_Wke[100 * 288];               // Wk with bk as col 272, zero-padded
__device__ float g_Pv[544 * 128];                // folded Wo@Wv, padded cols
__device__ float g_bo2[128];                     // folded Wo@bv + bo
__device__ int g_maskmode;                       // 0=int32, 1=uint8, 2=float32

// ---------------- mask dtype detection (deterministic, device-side) ----------------
__global__ void detect_mask_kernel(const unsigned int* __restrict__ w) {
    __shared__ int s_word_not01, s_byte_not01;
    if (threadIdx.x == 0) { s_word_not01 = 0; s_byte_not01 = 0; }
    __syncthreads();
    int bad_w = 0, bad_b = 0;
    for (int i = threadIdx.x; i < 1024; i += 256) {
        unsigned v = w[i];
        if (v > 1u) bad_w = 1;
        #pragma unroll
        for (int b = 0; b < 4; b++) {
            unsigned by = (v >> (8 * b)) & 0xffu;
            if (by > 1u) bad_b = 1;
        }
    }
    if (bad_w) atomicOr(&s_word_not01, 1);
    if (bad_b) atomicOr(&s_byte_not01, 1);
    __syncthreads();
    if (threadIdx.x == 0)
        g_maskmode = (s_word_not01 == 0) ? 0 : ((s_byte_not01 == 0) ? 1 : 2);
}

// ---------------- setup: build folded weights ----------------
__global__ void setup_kernel(const float* __restrict__ Wq, const float* __restrict__ Wk,
                             const float* __restrict__ Wv, const float* __restrict__ b_in,
                             const float* __restrict__ Wo, const float* __restrict__ bo) {
    int idx = blockIdx.x * blockDim.x + threadIdx.x;
    if (idx < 12800) {                 // W1[t][col] = Wq[col][t]
        int t = idx >> 7, col = idx & 127;
        g_W1[idx] = (col < 100) ? Wq[col * 100 + t] : 0.f;
    }
    if (idx < 28800) {                 // Wke[k][c]: Wk cols + bk at c=272
        int k = idx / 288, c = idx % 288;
        float v = 0.f;
        if (c < 272) v = Wk[k * 272 + c];
        else if (c == 272) v = b_in[100 + k];
        g_Wke[idx] = v;
    }
    if (idx < 128) {                   // bo2 = Wo @ bv + bo
        float v = 0.f;
        if (idx < 100) {
            v = bo[idx];
            for (int j = 0; j < 100; j++) v += Wo[idx * 100 + j] * b_in[200 + j];
        }
        g_bo2[idx] = v;
    }
    if (idx < 69632) {                 // Pv[h*272+c][i] = sum_j Wo[i, h*50+j] * Wv[h*50+j, c]
        int kk = idx >> 7, i = idx & 127;
        int h = kk / 272, c = kk % 272;
        float v = 0.f;
        if (i < 100) {
            #pragma unroll 5
            for (int j = 0; j < 50; j++)
                v += Wo[i * 100 + h * 50 + j] * Wv[(h * 50 + j) * 272 + c];
        }
        g_Pv[idx] = v;
    }
}

// ---------------- K1: qs = (st @ Wq^T + bq) * d^-0.5 ----------------
__global__ __launch_bounds__(256) void k1_qproj(const float* __restrict__ st,
                                                const float* __restrict__ b_in) {
    extern __shared__ float sm[];
    float* Ws = sm;                    // 100*128
    float* xs = sm + 12800;            // 32*100
    int tid = threadIdx.x;
    int b0 = blockIdx.x * 32;
    for (int i = tid; i < 12800; i += 256) Ws[i] = g_W1[i];
    for (int i = tid; i < 3200; i += 256) xs[i] = st[(size_t)b0 * 100 + i];
    __syncthreads();
    int warp = tid >> 5, lane = tid & 31;
    int bb = warp * 4;
    float acc[4][4];
    #pragma unroll
    for (int i = 0; i < 4; i++)
        #pragma unroll
        for (int u = 0; u < 4; u++) acc[i][u] = 0.f;
    #pragma unroll 1
    for (int k = 0; k < 100; k += 4) {
        float4 xv[4];
        #pragma unroll
        for (int i = 0; i < 4; i++)
            xv[i] = *(const float4*)&xs[(bb + i) * 100 + k];
        #pragma unroll
        for (int q = 0; q < 4; q++) {
            float w[4];
            #pragma unroll
            for (int u = 0; u < 4; u++) w[u] = Ws[(k + q) * 128 + lane + 32 * u];
            #pragma unroll
            for (int i = 0; i < 4; i++) {
                float x = (q == 0) ? xv[i].x : (q == 1) ? xv[i].y : (q == 2) ? xv[i].z : xv[i].w;
                #pragma unroll
                for (int u = 0; u < 4; u++) acc[i][u] += x * w[u];
            }
        }
    }
    const float dscale = 0.14142135623730951f;   // 1/sqrt(50)
    #pragma unroll
    for (int u = 0; u < 4; u++) {
        int col = lane + 32 * u;
        if (col < 100) {
            float bias = b_in[col];
            #pragma unroll
            for (int i = 0; i < 4; i++)
                g_qs[(size_t)(b0 + bb + i) * 100 + col] = (acc[i][u] + bias) * dscale;
        }
    }
}

// ---------------- K2: A[b, h*273+c] = sum_j qs[b, h*50+j] * Wke[h*50+j, c] ----------------
__global__ __launch_bounds__(256) void k2_aproj() {
    extern __shared__ float sm[];
    float* Ws = sm;                    // 100*288
    float* xs = sm + 28800;            // 32*100
    int tid = threadIdx.x;
    int b0 = blockIdx.x * 32;
    for (int i = tid; i < 28800; i += 256) Ws[i] = g_Wke[i];
    for (int i = tid; i < 3200; i += 256) xs[i] = g_qs[(size_t)b0 * 100 + i];
    __syncthreads();
    int warp = tid >> 5, lane = tid & 31;
    int bb = warp * 4;
    #pragma unroll 1
    for (int h = 0; h < 2; h++) {
        float acc[4][9];
        #pragma unroll
        for (int i = 0; i < 4; i++)
            #pragma unroll
            for (int u = 0; u < 9; u++) acc[i][u] = 0.f;
        #pragma unroll 1
        for (int kk = 0; kk < 50; kk += 2) {
            float2 xv[4];
            #pragma unroll
            for (int i = 0; i < 4; i++)
                xv[i] = *(const float2*)&xs[(bb + i) * 100 + h * 50 + kk];
            #pragma unroll
            for (int q = 0; q < 2; q++) {
                float w[9];
                #pragma unroll
                for (int u = 0; u < 9; u++)
                    w[u] = Ws[(h * 50 + kk + q) * 288 + lane + 32 * u];
                #pragma unroll
                for (int i = 0; i < 4; i++) {
                    float x = q ? xv[i].y : xv[i].x;
                    #pragma unroll
                    for (int u = 0; u < 9; u++) acc[i][u] += x * w[u];
                }
            }
        }
        #pragma unroll
        for (int u = 0; u < 9; u++) {
            int col = lane + 32 * u;
            if (col < 273) {
                #pragma unroll
                for (int i = 0; i < 4; i++)
                    g_A[(size_t)(b0 + bb + i) * 548 + h * 273 + col] = acc[i][u];
            }
        }
    }
}

// ---------------- K3: attention with online softmax; single kv pass ----------------
__global__ __launch_bounds__(256) void k3_attn(const float* __restrict__ nf,
                                               const float* __restrict__ ntf,
                                               const void* __restrict__ maskp,
                                               float* __restrict__ d_out) {
    int warp = threadIdx.x >> 5, lane = threadIdx.x & 31;
    size_t b = (size_t)blockIdx.x * 8 + warp;

    const float* Ab = g_A + b * 548;
    float aA0[9], aA1[9];
    #pragma unroll
    for (int u = 0; u < 9; u++) {
        int c = lane + 32 * u;
        aA0[u] = (c < 272) ? Ab[c] : 0.f;
        aA1[u] = (c < 272) ? Ab[273 + c] : 0.f;
    }
    float sb0 = Ab[272], sb1 = Ab[273 + 272];

    // read padding mask with runtime-detected dtype
    int mode = g_maskmode;
    bool masked = true;
    if (lane < 20) {
        size_t mi = b * 20 + lane;
        if (mode == 0)      masked = ((const int*)maskp)[mi] != 0;
        else if (mode == 1) masked = ((const unsigned char*)maskp)[mi] != 0;
        else                masked = ((const float*)maskp)[mi] != 0.f;
    }
    unsigned validbits = __ballot_sync(0xffffffffu, (lane < 20) && !masked);
    float* wavg = d_out + (size_t)BATCH * 100 + b * 20;
    if (validbits == 0) {
        if (lane == 0) g_invalid[b] = 1;
        if (lane < 20) wavg[lane] = 0.f;
        return;
    }
    if (lane == 0) g_invalid[b] = 0;

    float M0 = -__int_as_float(0x7f800000), M1 = M0;  // -inf
    float Z0 = 0.f, Z1 = 0.f;
    float acc0[9], acc1[9];
    #pragma unroll
    for (int u = 0; u < 9; u++) { acc0[u] = 0.f; acc1[u] = 0.f; }
    float s0l = M0, s1l = M1;

    #pragma unroll 1
    for (int n = 0; n < NNEI; n++) {
        if (!((validbits >> n) & 1u)) continue;
        const float* nr = nf + ((size_t)b * NNEI + n) * NFEAT;
        const float* tr = ntf + ((size_t)b * NNEI + n) * NTIME;
        float kv[9];
        #pragma unroll
        for (int u = 0; u < 9; u++) {
            int c = lane + 32 * u;
            kv[u] = (c < NFEAT) ? nr[c] : ((c < 272) ? tr[c - NFEAT] : 0.f);
        }
        float p0 = 0.f, p1 = 0.f;
        #pragma unroll
        for (int u = 0; u < 9; u++) { p0 += aA0[u] * kv[u]; p1 += aA1[u] * kv[u]; }
        #pragma unroll
        for (int o = 16; o; o >>= 1) {
            p0 += __shfl_xor_sync(0xffffffffu, p0, o);
            p1 += __shfl_xor_sync(0xffffffffu, p1, o);
        }
        float s0 = p0 + sb0, s1 = p1 + sb1;
        if (lane == n) { s0l = s0; s1l = s1; }
        float M0n = fmaxf(M0, s0);
        float a0 = __expf(M0 - M0n), e0 = __expf(s0 - M0n);
        Z0 = Z0 * a0 + e0; M0 = M0n;
        float M1n = fmaxf(M1, s1);
        float a1 = __expf(M1 - M1n), e1 = __expf(s1 - M1n);
        Z1 = Z1 * a1 + e1; M1 = M1n;
        #pragma unroll
        for (int u = 0; u < 9; u++) {
            acc0[u] = acc0[u] * a0 + e0 * kv[u];
            acc1[u] = acc1[u] * a1 + e1 * kv[u];
        }
    }
    float iZ0 = 1.f / Z0, iZ1 = 1.f / Z1;
    float* mb = g_m + b * 544;
    #pragma unroll
    for (int u = 0; u < 9; u++) {
        int c = lane + 32 * u;
        if (c < 272) {
            mb[c] = acc0[u] * iZ0;
            mb[272 + c] = acc1[u] * iZ1;
        }
    }
    if (lane < 20)
        wavg[lane] = 0.5f * (__expf(s0l - M0) * iZ0 + __expf(s1l - M1) * iZ1);
}

// ---------------- K4: out = m @ Pv + bo2, zeroed where invalid ----------------
__global__ __launch_bounds__(256) void k4_out(float* __restrict__ d_out) {
    extern __shared__ float sm[];
    float* Pvs = sm;                   // 272*128 (one k-tile)
    float* ms = sm + 272 * 128;        // 32*544
    int tid = threadIdx.x;
    int b0 = blockIdx.x * 32;
    for (int i = tid; i < 32 * 544; i += 256) ms[i] = g_m[(size_t)b0 * 544 + i];
    int warp = tid >> 5, lane = tid & 31;
    int bb = warp * 4;
    float acc[4][4];
    #pragma unroll
    for (int i = 0; i < 4; i++)
        #pragma unroll
        for (int u = 0; u < 4; u++) acc[i][u] = 0.f;
    #pragma unroll 1
    for (int kt = 0; kt < 2; kt++) {
        if (kt) __syncthreads();
        for (int i = tid; i < 272 * 128; i += 256) Pvs[i] = g_Pv[kt * 272 * 128 + i];
        __syncthreads();
        #pragma unroll 1
        for (int k = 0; k < 272; k += 4) {
            float4 xv[4];
            #pragma unroll
            for (int i = 0; i < 4; i++)
                xv[i] = *(const float4*)&ms[(bb + i) * 544 + kt * 272 + k];
            #pragma unroll
            for (int q = 0; q < 4; q++) {
                float w[4];
                #pragma unroll
                for (int u = 0; u < 4; u++) w[u] = Pvs[(k + q) * 128 + lane + 32 * u];
                #pragma unroll
                for (int i = 0; i < 4; i++) {
                    float x = (q == 0) ? xv[i].x : (q == 1) ? xv[i].y : (q == 2) ? xv[i].z : xv[i].w;
                    #pragma unroll
                    for (int u = 0; u < 4; u++) acc[i][u] += x * w[u];
                }
            }
        }
    }
    #pragma unroll
    for (int u = 0; u < 4; u++) {
        int col = lane + 32 * u;
        if (col < 100) {
            float bias = g_bo2[col];
            #pragma unroll
            for (int i = 0; i < 4; i++) {
                int bidx = b0 + bb + i;
                float r = g_invalid[bidx] ? 0.f : (acc[i][u] + bias);
                d_out[(size_t)bidx * 100 + col] = r;
            }
        }
    }
}

extern "C" void kernel_launch(void* const* d_in, const int* in_sizes, int n_in,
                              void* d_out, int out_size) {
    (void)in_sizes; (void)n_in; (void)out_size;
    const float* st   = (const float*)d_in[0];
    const float* nf   = (const float*)d_in[1];
    const float* ntf  = (const float*)d_in[2];
    const void*  mask = d_in[3];
    const float* Wq   = (const float*)d_in[4];
    const float* Wk   = (const float*)d_in[5];
    const float* Wv   = (const float*)d_in[6];
    const float* b_in = (const float*)d_in[7];
    const float* Wo   = (const float*)d_in[8];
    const float* bo   = (const float*)d_in[9];
    float* out = (float*)d_out;

    cudaFuncSetAttribute(k1_qproj, cudaFuncAttributeMaxDynamicSharedMemorySize, 64000);
    cudaFuncSetAttribute(k2_aproj, cudaFuncAttributeMaxDynamicSharedMemorySize, 128000);
    cudaFuncSetAttribute(k4_out,   cudaFuncAttributeMaxDynamicSharedMemorySize, 208896);

    detect_mask_kernel<<<1, 256>>>((const unsigned int*)mask);
    setup_kernel<<<272, 256>>>(Wq, Wk, Wv, b_in, Wo, bo);
    k1_qproj<<<BATCH / 32, 256, 64000>>>(st, b_in);
    k2_aproj<<<BATCH / 32, 256, 128000>>>();
    k3_attn<<<BATCH / 8, 256>>>(nf, ntf, mask, out);
    k4_out<<<BATCH / 32, 256, 208896>>>(out);
}

// round 3
// speedup vs baseline: 1.7736x; 1.7736x over previous
#include <cuda_runtime.h>

#define BATCH 131072
#define NNEI 20
#define NFEAT 172
#define NTIME 100

// ---- scratch (device globals; no allocations) ----
__device__ float g_qs[(size_t)BATCH * 100];      // scaled q
__device__ float g_A[(size_t)BATCH * 548];       // folded score matrix (2 heads x 273, col272 = bias)
__device__ float g_m[(size_t)BATCH * 544];       // weighted kv sums
__device__ unsigned char g_invalid[BATCH];
__device__ float g_W1[100 * 128];                // Wq^T, padded cols
__device__ float g_Wke2[2 * 50 * 320];           // per-head Wk (+bk col 272), padded to 320 cols
__device__ float g_Pv[544 * 128];                // folded Wo@Wv, padded cols
__device__ float g_bo2[128];                     // folded Wo@bv + bo
__device__ int g_maskmode;                       // 0=int32, 1=uint8, 2=float32

// ---- packed f32x2 helpers ----
__device__ __forceinline__ void fma2(unsigned long long& d, unsigned long long a, unsigned long long b) {
    asm("fma.rn.f32x2 %0, %1, %2, %0;" : "+l"(d) : "l"(a), "l"(b));
}
__device__ __forceinline__ unsigned long long pk2(float x, float y) {
    unsigned long long r; asm("mov.b64 %0, {%1,%2};" : "=l"(r) : "f"(x), "f"(y)); return r;
}
__device__ __forceinline__ float2 upk2(unsigned long long v) {
    float2 r; asm("mov.b64 {%0,%1}, %2;" : "=f"(r.x), "=f"(r.y) : "l"(v)); return r;
}

// ---------------- mask dtype detection ----------------
__global__ void detect_mask_kernel(const unsigned int* __restrict__ w) {
    __shared__ int s_word_not01, s_byte_not01;
    if (threadIdx.x == 0) { s_word_not01 = 0; s_byte_not01 = 0; }
    __syncthreads();
    int bad_w = 0, bad_b = 0;
    for (int i = threadIdx.x; i < 1024; i += 256) {
        unsigned v = w[i];
        if (v > 1u) bad_w = 1;
        #pragma unroll
        for (int b = 0; b < 4; b++) {
            unsigned by = (v >> (8 * b)) & 0xffu;
            if (by > 1u) bad_b = 1;
        }
    }
    if (bad_w) atomicOr(&s_word_not01, 1);
    if (bad_b) atomicOr(&s_byte_not01, 1);
    __syncthreads();
    if (threadIdx.x == 0)
        g_maskmode = (s_word_not01 == 0) ? 0 : ((s_byte_not01 == 0) ? 1 : 2);
}

// ---------------- setup: build folded weights ----------------
__global__ void setup_kernel(const float* __restrict__ Wq, const float* __restrict__ Wk,
                             const float* __restrict__ Wv, const float* __restrict__ b_in,
                             const float* __restrict__ Wo, const float* __restrict__ bo) {
    int idx = blockIdx.x * blockDim.x + threadIdx.x;
    if (idx < 12800) {                 // W1[t][col] = Wq[col][t]
        int t = idx >> 7, col = idx & 127;
        g_W1[idx] = (col < 100) ? Wq[col * 100 + t] : 0.f;
    }
    if (idx < 32000) {                 // Wke2[h][k][c]
        int h = idx / 16000, rem = idx % 16000;
        int k = rem / 320, c = rem % 320;
        int kg = h * 50 + k;
        float v = 0.f;
        if (c < 272) v = Wk[kg * 272 + c];
        else if (c == 272) v = b_in[100 + kg];
        g_Wke2[idx] = v;
    }
    if (idx < 128) {                   // bo2 = Wo @ bv + bo
        float v = 0.f;
        if (idx < 100) {
            v = bo[idx];
            for (int j = 0; j < 100; j++) v += Wo[idx * 100 + j] * b_in[200 + j];
        }
        g_bo2[idx] = v;
    }
    if (idx < 69632) {                 // Pv[h*272+c][i] = sum_j Wo[i, h*50+j] * Wv[h*50+j, c]
        int kk = idx >> 7, i = idx & 127;
        int h = kk / 272, c = kk % 272;
        float v = 0.f;
        if (i < 100) {
            #pragma unroll 5
            for (int j = 0; j < 50; j++)
                v += Wo[i * 100 + h * 50 + j] * Wv[(h * 50 + j) * 272 + c];
        }
        g_Pv[idx] = v;
    }
}

// ---------------- K1: qs = (st @ Wq^T + bq) * d^-0.5 ; 8 batches/warp, f32x2 ----------------
__global__ __launch_bounds__(256, 2) void k1_qproj(const float* __restrict__ st,
                                                   const float* __restrict__ b_in) {
    extern __shared__ float sm[];
    float* Ws = sm;                    // 100*128
    int tid = threadIdx.x;
    for (int i = tid; i < 12800 / 4; i += 256)
        ((float4*)Ws)[i] = ((const float4*)g_W1)[i];
    __syncthreads();
    int warp = tid >> 5, lane = tid & 31;
    size_t b0 = (size_t)blockIdx.x * 64 + warp * 8;
    unsigned long long acc[8][2];
    #pragma unroll
    for (int i = 0; i < 8; i++) { acc[i][0] = 0ull; acc[i][1] = 0ull; }
    int wbase = lane * 2;
    #pragma unroll 1
    for (int k = 0; k < 100; k += 4) {
        float4 xv[8];
        #pragma unroll
        for (int i = 0; i < 8; i++)
            xv[i] = *(const float4*)(st + (b0 + i) * 100 + k);
        #pragma unroll
        for (int q = 0; q < 4; q++) {
            unsigned long long w0 = *(const unsigned long long*)&Ws[(k + q) * 128 + wbase];
            unsigned long long w1 = *(const unsigned long long*)&Ws[(k + q) * 128 + wbase + 64];
            #pragma unroll
            for (int i = 0; i < 8; i++) {
                float x = (q == 0) ? xv[i].x : (q == 1) ? xv[i].y : (q == 2) ? xv[i].z : xv[i].w;
                unsigned long long xd = pk2(x, x);
                fma2(acc[i][0], xd, w0);
                fma2(acc[i][1], xd, w1);
            }
        }
    }
    const float dscale = 0.14142135623730951f;   // 1/sqrt(50)
    #pragma unroll
    for (int u = 0; u < 2; u++) {
        int c0 = lane * 2 + 64 * u;
        if (c0 < 100) {
            float bx = b_in[c0];
            float by = (c0 + 1 < 100) ? b_in[c0 + 1] : 0.f;
            #pragma unroll
            for (int i = 0; i < 8; i++) {
                float2 v = upk2(acc[i][u]);
                v.x = (v.x + bx) * dscale;
                v.y = (v.y + by) * dscale;
                if (c0 + 1 < 100)
                    *(float2*)(g_qs + (b0 + i) * 100 + c0) = v;
                else
                    g_qs[(b0 + i) * 100 + c0] = v.x;
            }
        }
    }
}

// ---------------- K2: A[b, h*273+c] = sum_k qs[b,h*50+k] * Wke2[h][k][c]; 4 batches/warp, f32x2 ----------------
__global__ __launch_bounds__(256, 2) void k2_aproj() {
    extern __shared__ float sm[];
    float* Ws = sm;                    // 50*320
    int tid = threadIdx.x;
    int h = blockIdx.y;
    for (int i = tid; i < 16000 / 4; i += 256)
        ((float4*)Ws)[i] = ((const float4*)(g_Wke2 + h * 16000))[i];
    __syncthreads();
    int warp = tid >> 5, lane = tid & 31;
    size_t b0 = (size_t)blockIdx.x * 32 + warp * 4;
    unsigned long long acc[4][5];
    #pragma unroll
    for (int i = 0; i < 4; i++)
        #pragma unroll
        for (int u = 0; u < 5; u++) acc[i][u] = 0ull;
    int wbase = lane * 2;
    const float* xb = g_qs + h * 50;
    #pragma unroll 1
    for (int k = 0; k < 50; k += 2) {
        float2 xv[4];
        #pragma unroll
        for (int i = 0; i < 4; i++)
            xv[i] = *(const float2*)(xb + (b0 + i) * 100 + k);
        #pragma unroll
        for (int q = 0; q < 2; q++) {
            unsigned long long w2[5];
            #pragma unroll
            for (int u = 0; u < 5; u++)
                w2[u] = *(const unsigned long long*)&Ws[(k + q) * 320 + wbase + 64 * u];
            #pragma unroll
            for (int i = 0; i < 4; i++) {
                float x = q ? xv[i].y : xv[i].x;
                unsigned long long xd = pk2(x, x);
                #pragma unroll
                for (int u = 0; u < 5; u++) fma2(acc[i][u], xd, w2[u]);
            }
        }
    }
    #pragma unroll
    for (int u = 0; u < 5; u++) {
        int c0 = lane * 2 + 64 * u;
        #pragma unroll
        for (int i = 0; i < 4; i++) {
            float2 v = upk2(acc[i][u]);
            float* Ar = g_A + (b0 + i) * 548 + h * 273;
            if (c0 < 273) Ar[c0] = v.x;
            if (c0 + 1 < 273) Ar[c0 + 1] = v.y;
        }
    }
}

// ---------------- K3: attention with online softmax; single kv pass ----------------
__global__ __launch_bounds__(256) void k3_attn(const float* __restrict__ nf,
                                               const float* __restrict__ ntf,
                                               const void* __restrict__ maskp,
                                               float* __restrict__ d_out) {
    int warp = threadIdx.x >> 5, lane = threadIdx.x & 31;
    size_t b = (size_t)blockIdx.x * 8 + warp;

    const float* Ab = g_A + b * 548;
    float aA0[9], aA1[9];
    #pragma unroll
    for (int u = 0; u < 9; u++) {
        int c = lane + 32 * u;
        aA0[u] = (c < 272) ? Ab[c] : 0.f;
        aA1[u] = (c < 272) ? Ab[273 + c] : 0.f;
    }
    float sb0 = Ab[272], sb1 = Ab[273 + 272];

    int mode = g_maskmode;
    bool masked = true;
    if (lane < 20) {
        size_t mi = b * 20 + lane;
        if (mode == 0)      masked = ((const int*)maskp)[mi] != 0;
        else if (mode == 1) masked = ((const unsigned char*)maskp)[mi] != 0;
        else                masked = ((const float*)maskp)[mi] != 0.f;
    }
    unsigned validbits = __ballot_sync(0xffffffffu, (lane < 20) && !masked);
    float* wavg = d_out + (size_t)BATCH * 100 + b * 20;
    if (validbits == 0) {
        if (lane == 0) g_invalid[b] = 1;
        if (lane < 20) wavg[lane] = 0.f;
        return;
    }
    if (lane == 0) g_invalid[b] = 0;

    float M0 = -__int_as_float(0x7f800000), M1 = M0;  // -inf
    float Z0 = 0.f, Z1 = 0.f;
    float acc0[9], acc1[9];
    #pragma unroll
    for (int u = 0; u < 9; u++) { acc0[u] = 0.f; acc1[u] = 0.f; }
    float s0l = M0, s1l = M1;

    #pragma unroll 1
    for (int n = 0; n < NNEI; n++) {
        if (!((validbits >> n) & 1u)) continue;
        const float* nr = nf + ((size_t)b * NNEI + n) * NFEAT;
        const float* tr = ntf + ((size_t)b * NNEI + n) * NTIME;
        float kv[9];
        #pragma unroll
        for (int u = 0; u < 9; u++) {
            int c = lane + 32 * u;
            kv[u] = (c < NFEAT) ? nr[c] : ((c < 272) ? tr[c - NFEAT] : 0.f);
        }
        float p0 = 0.f, p1 = 0.f;
        #pragma unroll
        for (int u = 0; u < 9; u++) { p0 += aA0[u] * kv[u]; p1 += aA1[u] * kv[u]; }
        #pragma unroll
        for (int o = 16; o; o >>= 1) {
            p0 += __shfl_xor_sync(0xffffffffu, p0, o);
            p1 += __shfl_xor_sync(0xffffffffu, p1, o);
        }
        float s0 = p0 + sb0, s1 = p1 + sb1;
        if (lane == n) { s0l = s0; s1l = s1; }
        float M0n = fmaxf(M0, s0);
        float a0 = __expf(M0 - M0n), e0 = __expf(s0 - M0n);
        Z0 = Z0 * a0 + e0; M0 = M0n;
        float M1n = fmaxf(M1, s1);
        float a1 = __expf(M1 - M1n), e1 = __expf(s1 - M1n);
        Z1 = Z1 * a1 + e1; M1 = M1n;
        #pragma unroll
        for (int u = 0; u < 9; u++) {
            acc0[u] = acc0[u] * a0 + e0 * kv[u];
            acc1[u] = acc1[u] * a1 + e1 * kv[u];
        }
    }
    float iZ0 = 1.f / Z0, iZ1 = 1.f / Z1;
    float* mb = g_m + b * 544;
    #pragma unroll
    for (int u = 0; u < 9; u++) {
        int c = lane + 32 * u;
        if (c < 272) {
            mb[c] = acc0[u] * iZ0;
            mb[272 + c] = acc1[u] * iZ1;
        }
    }
    if (lane < 20)
        wavg[lane] = 0.5f * (__expf(s0l - M0) * iZ0 + __expf(s1l - M1) * iZ1);
}

// ---------------- K4: out = m @ Pv + bo2; 8 batches/warp, f32x2, 4 k-tiles ----------------
__global__ __launch_bounds__(256, 2) void k4_out(float* __restrict__ d_out) {
    extern __shared__ float sm[];
    float* Pvs = sm;                   // 136*128 k-tile
    int tid = threadIdx.x;
    int warp = tid >> 5, lane = tid & 31;
    size_t b0 = (size_t)blockIdx.x * 64 + warp * 8;
    unsigned long long acc[8][2];
    #pragma unroll
    for (int i = 0; i < 8; i++) { acc[i][0] = 0ull; acc[i][1] = 0ull; }
    int wbase = lane * 2;
    #pragma unroll 1
    for (int kt = 0; kt < 4; kt++) {
        if (kt) __syncthreads();
        {
            const float4* src = (const float4*)(g_Pv + kt * 136 * 128);
            for (int i = tid; i < 136 * 128 / 4; i += 256)
                ((float4*)Pvs)[i] = src[i];
        }
        __syncthreads();
        const float* mbase = g_m + kt * 136;
        #pragma unroll 1
        for (int k = 0; k < 136; k += 4) {
            float4 xv[8];
            #pragma unroll
            for (int i = 0; i < 8; i++)
                xv[i] = *(const float4*)(mbase + (b0 + i) * 544 + k);
            #pragma unroll
            for (int q = 0; q < 4; q++) {
                unsigned long long w0 = *(const unsigned long long*)&Pvs[(k + q) * 128 + wbase];
                unsigned long long w1 = *(const unsigned long long*)&Pvs[(k + q) * 128 + wbase + 64];
                #pragma unroll
                for (int i = 0; i < 8; i++) {
                    float x = (q == 0) ? xv[i].x : (q == 1) ? xv[i].y : (q == 2) ? xv[i].z : xv[i].w;
                    unsigned long long xd = pk2(x, x);
                    fma2(acc[i][0], xd, w0);
                    fma2(acc[i][1], xd, w1);
                }
            }
        }
    }
    #pragma unroll
    for (int u = 0; u < 2; u++) {
        int c0 = lane * 2 + 64 * u;
        if (c0 < 100) {
            float bx = g_bo2[c0];
            float by = (c0 + 1 < 100) ? g_bo2[c0 + 1] : 0.f;
            #pragma unroll
            for (int i = 0; i < 8; i++) {
                float2 v = upk2(acc[i][u]);
                bool inv = g_invalid[b0 + i];
                v.x = inv ? 0.f : (v.x + bx);
                v.y = inv ? 0.f : (v.y + by);
                if (c0 + 1 < 100)
                    *(float2*)(d_out + (b0 + i) * 100 + c0) = v;
                else
                    d_out[(b0 + i) * 100 + c0] = v.x;
            }
        }
    }
}

extern "C" void kernel_launch(void* const* d_in, const int* in_sizes, int n_in,
                              void* d_out, int out_size) {
    (void)in_sizes; (void)n_in; (void)out_size;
    const float* st   = (const float*)d_in[0];
    const float* nf   = (const float*)d_in[1];
    const float* ntf  = (const float*)d_in[2];
    const void*  mask = d_in[3];
    const float* Wq   = (const float*)d_in[4];
    const float* Wk   = (const float*)d_in[5];
    const float* Wv   = (const float*)d_in[6];
    const float* b_in = (const float*)d_in[7];
    const float* Wo   = (const float*)d_in[8];
    const float* bo   = (const float*)d_in[9];
    float* out = (float*)d_out;

    cudaFuncSetAttribute(k1_qproj, cudaFuncAttributeMaxDynamicSharedMemorySize, 51200);
    cudaFuncSetAttribute(k2_aproj, cudaFuncAttributeMaxDynamicSharedMemorySize, 64000);
    cudaFuncSetAttribute(k4_out,   cudaFuncAttributeMaxDynamicSharedMemorySize, 69632);

    detect_mask_kernel<<<1, 256>>>((const unsigned int*)mask);
    setup_kernel<<<272, 256>>>(Wq, Wk, Wv, b_in, Wo, bo);
    k1_qproj<<<BATCH / 64, 256, 51200>>>(st, b_in);
    k2_aproj<<<dim3(BATCH / 32, 2), 256, 64000>>>();
    k3_attn<<<BATCH / 8, 256>>>(nf, ntf, mask, out);
    k4_out<<<BATCH / 64, 256, 69632>>>(out);
}